// round 14
// baseline (speedup 1.0000x reference)
#include <cuda_runtime.h>
#include <cuda_bf16.h>
#include <math.h>
#include <stdint.h>

// Problem constants: N=100000, H=128, E=500000, G=3
#define MAX_E      600000
#define MAX_NODES  100608
#define CHUNK      128
#define MAX_CHUNKS ((MAX_E + CHUNK - 1) / CHUNK)

__device__ int d_perm[MAX_E];
__device__ int d_chunkCnt[MAX_CHUNKS * 3];
__device__ int d_chunkOff[MAX_CHUNKS * 3];
__device__ int d_groupStart[4];
__device__ int d_tileBase[4];

__device__ unsigned short d_emb_hi[MAX_NODES * 128];
__device__ unsigned short d_emb_lo[MAX_NODES * 128];
__device__ unsigned short d_w1t_hi[3 * 128 * 256];   // [g][n=128][k=256]
__device__ unsigned short d_w1t_lo[3 * 128 * 256];
__device__ unsigned short d_w2t_hi[3 * 64 * 128];    // [g][n=64][k=128]
__device__ unsigned short d_w2t_lo[3 * 64 * 128];

// ======================= helpers ============================================
__device__ __forceinline__ uint32_t smem_u32(const void* p) {
    uint32_t a;
    asm("{ .reg .u64 t; cvta.to.shared.u64 t, %1; cvt.u32.u64 %0, t; }"
        : "=r"(a) : "l"(p));
    return a;
}
__device__ __forceinline__ void ldsm4(uint32_t& r0, uint32_t& r1,
                                      uint32_t& r2, uint32_t& r3, uint32_t a) {
    asm volatile("ldmatrix.sync.aligned.m8n8.x4.shared.b16 {%0,%1,%2,%3}, [%4];"
        : "=r"(r0), "=r"(r1), "=r"(r2), "=r"(r3) : "r"(a));
}
__device__ __forceinline__ void mma_bf16(float* d, const uint32_t* a,
                                         uint32_t b0, uint32_t b1) {
    asm volatile("mma.sync.aligned.m16n8k16.row.col.f32.bf16.bf16.f32 "
        "{%0,%1,%2,%3}, {%4,%5,%6,%7}, {%8,%9}, {%0,%1,%2,%3};"
        : "+f"(d[0]), "+f"(d[1]), "+f"(d[2]), "+f"(d[3])
        : "r"(a[0]), "r"(a[1]), "r"(a[2]), "r"(a[3]), "r"(b0), "r"(b1));
}
__device__ __forceinline__ uint32_t pack_bf16x2(float x, float y) {
    __nv_bfloat162 v = __floats2bfloat162_rn(x, y);
    return *reinterpret_cast<uint32_t*>(&v);
}
#define CP16(dst, src) \
    asm volatile("cp.async.cg.shared.global [%0], [%1], 16;" \
        :: "r"(dst), "l"(src) : "memory")
#define CP_COMMIT() asm volatile("cp.async.commit_group;" ::: "memory")
#define CP_WAIT_ALL() asm volatile("cp.async.wait_group 0;" ::: "memory")

// =========================== fused prep =====================================
__device__ __forceinline__ void split_bf16(float x, unsigned short& h, unsigned short& l) {
    __nv_bfloat16 hb = __float2bfloat16(x);
    float hf = __bfloat162float(hb);
    __nv_bfloat16 lb = __float2bfloat16(x - hf);
    h = __bfloat16_as_ushort(hb); l = __bfloat16_as_ushort(lb);
}

#define W1_ELEMS (3 * 256 * 128)
#define W2_ELEMS (3 * 128 * 64)

// blockIdx ranges: [0, embBlocks) emb(float4); then W1; then W2
__global__ void k_prep(const float* __restrict__ emb, int total4, int embBlocks,
                       const float* __restrict__ W1, int w1Blocks,
                       const float* __restrict__ W2) {
    int bb = blockIdx.x;
    if (bb < embBlocks) {
        int i = bb * 256 + threadIdx.x;
        if (i >= total4) return;
        float4 v = reinterpret_cast<const float4*>(emb)[i];
        ushort4 h, l;
        split_bf16(v.x, h.x, l.x); split_bf16(v.y, h.y, l.y);
        split_bf16(v.z, h.z, l.z); split_bf16(v.w, h.w, l.w);
        reinterpret_cast<ushort4*>(d_emb_hi)[i] = h;
        reinterpret_cast<ushort4*>(d_emb_lo)[i] = l;
    } else if (bb < embBlocks + w1Blocks) {
        int i = (bb - embBlocks) * 256 + threadIdx.x;
        if (i >= W1_ELEMS) return;
        int g = i / (256 * 128), r = i % (256 * 128);
        int d = r / 128, h = r % 128;
        int dst = (g * 128 + h) * 256 + d;
        split_bf16(W1[i], d_w1t_hi[dst], d_w1t_lo[dst]);
    } else {
        int i = (bb - embBlocks - w1Blocks) * 256 + threadIdx.x;
        if (i >= W2_ELEMS) return;
        int g = i / (128 * 64), r = i % (128 * 64);
        int k = r / 64, n = r % 64;
        int dst = (g * 64 + n) * 128 + k;
        split_bf16(W2[i], d_w2t_hi[dst], d_w2t_lo[dst]);
    }
}

// =================== fused count+scan (single CTA) ==========================
#define SCAN_T 512
__global__ void k_scan(const int* __restrict__ groups, int E, int nChunks) {
    __shared__ int sv[SCAN_T]; __shared__ int gtot[3]; __shared__ int gs[4];
    int tid = threadIdx.x;
    int per = (nChunks + SCAN_T - 1) / SCAN_T;
    int c0 = tid * per, c1 = c0 + per;
    if (c1 > nChunks) c1 = nChunks;
    if (c0 > nChunks) c0 = nChunks;

    int t[3] = {0, 0, 0};
    for (int c = c0; c < c1; c++) {
        int s = c * CHUNK, e = s + CHUNK; if (e > E) e = E;
        int cc0 = 0, cc1 = 0, cc2 = 0;
        for (int i = s; i < e; i++) {
            int g = groups[i];
            cc0 += (g == 0); cc1 += (g == 1); cc2 += (g == 2);
        }
        d_chunkCnt[c * 3 + 0] = cc0;
        d_chunkCnt[c * 3 + 1] = cc1;
        d_chunkCnt[c * 3 + 2] = cc2;
        t[0] += cc0; t[1] += cc1; t[2] += cc2;
    }
    int base[3];
    for (int g = 0; g < 3; g++) {
        sv[tid] = t[g];
        __syncthreads();
        for (int off = 1; off < SCAN_T; off <<= 1) {
            int v = (tid >= off) ? sv[tid - off] : 0;
            __syncthreads(); sv[tid] += v; __syncthreads();
        }
        base[g] = sv[tid] - t[g];
        if (tid == SCAN_T - 1) gtot[g] = sv[tid];
        __syncthreads();
    }
    if (tid == 0) {
        gs[0] = 0; gs[1] = gtot[0]; gs[2] = gtot[0] + gtot[1]; gs[3] = gs[2] + gtot[2];
        int tb = 0;
        for (int g = 0; g < 3; g++) {
            d_groupStart[g] = gs[g]; d_tileBase[g] = tb;
            tb += (gtot[g] + 127) >> 7;
        }
        d_groupStart[3] = gs[3]; d_tileBase[3] = tb;
    }
    __syncthreads();
    int run[3];
    for (int g = 0; g < 3; g++) run[g] = gs[g] + base[g];
    for (int c = c0; c < c1; c++)
        for (int g = 0; g < 3; g++) { d_chunkOff[c * 3 + g] = run[g]; run[g] += d_chunkCnt[c * 3 + g]; }
}

__global__ void k_scatter(const int* __restrict__ groups, int E, int nChunks) {
    int c = blockIdx.x * blockDim.x + threadIdx.x;
    if (c >= nChunks) return;
    int o0 = d_chunkOff[c * 3], o1 = d_chunkOff[c * 3 + 1], o2 = d_chunkOff[c * 3 + 2];
    int s = c * CHUNK, e = s + CHUNK; if (e > E) e = E;
    for (int i = s; i < e; i++) {
        int g = groups[i];
        int p = (g == 0) ? o0++ : (g == 1) ? o1++ : o2++;
        d_perm[p] = i;
    }
}

// =============================== main kernel ================================
// 128-edge tile, 256 threads = 8 warps (warp w: rows w*16..w*16+15).
// GEMM1: K=256 in 16 chunks of 16, cp.async double-buffered, XOR-swizzled.
// GEMM2: B2 padded rows (272B), prefetched via cp.async during epilogue1.

#define BST2 136   // B2 padded row stride in bf16 (128+8)

__global__ __launch_bounds__(256) void k_main(
    const int* __restrict__ edges,
    const float* __restrict__ b1, const float* __restrict__ lng,
    const float* __restrict__ lnb, const float* __restrict__ b2,
    const float* __restrict__ W3, const float* __restrict__ b3,
    float* __restrict__ out)
{
    __shared__ __align__(16) union {
        struct {
            unsigned short A[2][2][2048];   // [buf][hi/lo][128 rows x 16 k]
            unsigned short B[2][2][2048];
        } p1;                               // 32768 B
        struct {
            unsigned short B2h[64 * BST2]; unsigned short B2l[64 * BST2];
        } p2;                               // 34816 B
    } sm;
    __shared__ int sU[128], sV[128];
    __shared__ float s_b1[128], s_lng[128], s_lnb[128];
    __shared__ float s_b2[64], s_w3[64];

    int b = blockIdx.x;
    if (b >= d_tileBase[3]) return;
    int g = (b >= d_tileBase[1]) + (b >= d_tileBase[2]);
    int tileStart = d_groupStart[g] + (b - d_tileBase[g]) * 128;
    int nE = d_groupStart[g + 1] - tileStart;
    if (nE > 128) nE = 128;

    int tid = threadIdx.x;
    int w = tid >> 5, L = tid & 31;
    int lg = L >> 2, lt = L & 3;
    int m8 = L >> 3, r8 = L & 7;

    if (tid < 128) {
        int u = 0, v = 0;
        if (tid < nE) {
            int e = d_perm[tileStart + tid];
            u = edges[2 * e]; v = edges[2 * e + 1];
        }
        sU[tid] = u; sV[tid] = v;
        s_b1[tid]  = b1[g * 128 + tid];
        s_lng[tid] = lng[g * 128 + tid];
        s_lnb[tid] = lnb[g * 128 + tid];
    }
    if (tid < 64) { s_b2[tid] = b2[g * 64 + tid]; s_w3[tid] = W3[g * 64 + tid]; }
    __syncthreads();

    const unsigned short* w1h = d_w1t_hi + (size_t)g * 128 * 256;
    const unsigned short* w1l = d_w1t_lo + (size_t)g * 128 * 256;

    uint32_t baseA[2][2], baseB[2][2];
#pragma unroll
    for (int bu = 0; bu < 2; bu++)
#pragma unroll
        for (int hl = 0; hl < 2; hl++) {
            baseA[bu][hl] = smem_u32(&sm.p1.A[bu][hl][0]);
            baseB[bu][hl] = smem_u32(&sm.p1.B[bu][hl][0]);
        }

    auto issueChunk = [&](int chunk, int bu) {
        int kb = chunk * 16;
#pragma unroll
        for (int t = 0; t < 4; t++) {
            int idx = tid + t * 256;          // 0..1023
            if (idx < 512) {                  // A: 128 rows x 2 blk x 2 hl
                int row = idx >> 2;
                int hl = (idx >> 1) & 1;
                int blk = idx & 1;
                int node = (kb < 128) ? sU[row] : sV[row];
                const unsigned short* src = (hl ? d_emb_lo : d_emb_hi)
                    + (size_t)node * 128 + (kb & 127) + blk * 8;
                uint32_t dst = baseA[bu][hl]
                    + (uint32_t)(row * 32 + ((blk ^ ((row >> 2) & 1)) << 4));
                CP16(dst, src);
            } else {                          // B: 128 n x 2 blk x 2 hl
                int i = idx - 512;
                int n = i >> 2;
                int hl = (i >> 1) & 1;
                int blk = i & 1;
                const unsigned short* src = (hl ? w1l : w1h)
                    + (size_t)n * 256 + kb + blk * 8;
                uint32_t dst = baseB[bu][hl]
                    + (uint32_t)(n * 32 + ((blk ^ ((n >> 2) & 1)) << 4));
                CP16(dst, src);
            }
        }
    };

    // ---- GEMM1: D1[128,128] -----------------------------------------------
    float d1[16][4];
#pragma unroll
    for (int n = 0; n < 16; n++)
#pragma unroll
        for (int j = 0; j < 4; j++) d1[n][j] = 0.f;

    int aRow = w * 16 + r8 + (m8 & 1) * 8;
    int aBlk = m8 >> 1;
    uint32_t aOff = (uint32_t)(aRow * 32 + ((aBlk ^ ((aRow >> 2) & 1)) << 4));
    int bN = r8 + (m8 >> 1) * 8;
    int bBlk = m8 & 1;

    issueChunk(0, 0);
    CP_COMMIT();

    for (int c = 0; c < 16; c++) {
        int bu = c & 1;
        CP_WAIT_ALL();
        __syncthreads();
        if (c + 1 < 16) { issueChunk(c + 1, (c + 1) & 1); CP_COMMIT(); }

        uint32_t ah[4], al[4];
        ldsm4(ah[0], ah[1], ah[2], ah[3], baseA[bu][0] + aOff);
        ldsm4(al[0], al[1], al[2], al[3], baseA[bu][1] + aOff);
#pragma unroll
        for (int p = 0; p < 8; p++) {
            int bRow = 16 * p + bN;
            uint32_t boff = (uint32_t)(bRow * 32 + ((bBlk ^ ((bRow >> 2) & 1)) << 4));
            uint32_t bh0, bh1, bh2, bh3, bl0, bl1, bl2, bl3;
            ldsm4(bh0, bh1, bh2, bh3, baseB[bu][0] + boff);
            ldsm4(bl0, bl1, bl2, bl3, baseB[bu][1] + boff);
            mma_bf16(d1[2 * p],     ah, bh0, bh1);
            mma_bf16(d1[2 * p],     ah, bl0, bl1);
            mma_bf16(d1[2 * p],     al, bh0, bh1);
            mma_bf16(d1[2 * p + 1], ah, bh2, bh3);
            mma_bf16(d1[2 * p + 1], ah, bl2, bl3);
            mma_bf16(d1[2 * p + 1], al, bh2, bh3);
        }
    }
    __syncthreads();   // all reads of p1 done before B2 overwrites (union)

    // ---- prefetch B2 (W2T) via cp.async; overlapped with epilogue1 --------
    {
        const unsigned short* w2h = d_w2t_hi + (size_t)g * 64 * 128;
        const unsigned short* w2l = d_w2t_lo + (size_t)g * 64 * 128;
        uint32_t b2h = smem_u32(sm.p2.B2h), b2l = smem_u32(sm.p2.B2l);
#pragma unroll
        for (int t = 0; t < 8; t++) {
            int idx = tid + t * 256;          // 0..2047
            int hl = idx >> 10, i = idx & 1023;
            int n = i >> 4, q = i & 15;
            const unsigned short* src = (hl ? w2l : w2h) + (size_t)n * 128 + q * 8;
            uint32_t dst = (hl ? b2l : b2h) + (uint32_t)(n * 272 + q * 16);
            CP16(dst, src);
        }
        CP_COMMIT();
    }

    // ---- epilogue1: bias + LN + GELU; build GEMM2 A-frags in registers ----
    float sA = 0.f, sA2 = 0.f, sB = 0.f, sB2 = 0.f;
#pragma unroll
    for (int nt = 0; nt < 16; nt++) {
        int c0 = nt * 8 + 2 * lt;
        float v0 = d1[nt][0] + s_b1[c0];
        float v1 = d1[nt][1] + s_b1[c0 + 1];
        float v2 = d1[nt][2] + s_b1[c0];
        float v3 = d1[nt][3] + s_b1[c0 + 1];
        d1[nt][0] = v0; d1[nt][1] = v1; d1[nt][2] = v2; d1[nt][3] = v3;
        sA += v0 + v1; sA2 += v0 * v0 + v1 * v1;
        sB += v2 + v3; sB2 += v2 * v2 + v3 * v3;
    }
#pragma unroll
    for (int msk = 1; msk < 4; msk <<= 1) {
        sA  += __shfl_xor_sync(0xffffffffu, sA,  msk);
        sA2 += __shfl_xor_sync(0xffffffffu, sA2, msk);
        sB  += __shfl_xor_sync(0xffffffffu, sB,  msk);
        sB2 += __shfl_xor_sync(0xffffffffu, sB2, msk);
    }
    float muA = sA * (1.f / 128.f);
    float invA = rsqrtf(sA2 * (1.f / 128.f) - muA * muA + 1e-5f);
    float muB = sB * (1.f / 128.f);
    float invB = rsqrtf(sB2 * (1.f / 128.f) - muB * muB + 1e-5f);

    uint32_t ha[8][4], la[8][4];
#pragma unroll
    for (int nt = 0; nt < 16; nt++) {
        int c0 = nt * 8 + 2 * lt;
        float gl0 = s_lng[c0], gl1 = s_lng[c0 + 1];
        float bb0 = s_lnb[c0], bb1v = s_lnb[c0 + 1];
        float h0 = (d1[nt][0] - muA) * invA * gl0 + bb0;
        float h1 = (d1[nt][1] - muA) * invA * gl1 + bb1v;
        float h2 = (d1[nt][2] - muB) * invB * gl0 + bb0;
        float h3 = (d1[nt][3] - muB) * invB * gl1 + bb1v;
        h0 = h0 * normcdff(h0); h1 = h1 * normcdff(h1);
        h2 = h2 * normcdff(h2); h3 = h3 * normcdff(h3);
        float e0, e1, e2, e3;
        __nv_bfloat16 t0 = __float2bfloat16(h0); e0 = h0 - __bfloat162float(t0);
        __nv_bfloat16 t1 = __float2bfloat16(h1); e1 = h1 - __bfloat162float(t1);
        __nv_bfloat16 t2 = __float2bfloat16(h2); e2 = h2 - __bfloat162float(t2);
        __nv_bfloat16 t3 = __float2bfloat16(h3); e3 = h3 - __bfloat162float(t3);
        int s = nt >> 1, half = nt & 1;
        __nv_bfloat162 p01; p01.x = t0; p01.y = t1;
        __nv_bfloat162 p23; p23.x = t2; p23.y = t3;
        ha[s][half * 2 + 0] = *reinterpret_cast<uint32_t*>(&p01);
        ha[s][half * 2 + 1] = *reinterpret_cast<uint32_t*>(&p23);
        la[s][half * 2 + 0] = pack_bf16x2(e0, e1);
        la[s][half * 2 + 1] = pack_bf16x2(e2, e3);
    }

    CP_WAIT_ALL();
    __syncthreads();

    // ---- GEMM2: D2[128,64] = h[128,128] x W2T -----------------------------
    float d2[8][4];
#pragma unroll
    for (int n = 0; n < 8; n++)
#pragma unroll
        for (int j = 0; j < 4; j++) d2[n][j] = 0.f;

    uint32_t baseB2h = smem_u32(sm.p2.B2h), baseB2l = smem_u32(sm.p2.B2l);
#pragma unroll
    for (int s = 0; s < 8; s++) {
#pragma unroll
        for (int p = 0; p < 4; p++) {
            uint32_t boff = (uint32_t)(((16 * p + bN) * BST2 + s * 16 + bBlk * 8) * 2);
            uint32_t bh0, bh1, bh2, bh3, bl0, bl1, bl2, bl3;
            ldsm4(bh0, bh1, bh2, bh3, baseB2h + boff);
            ldsm4(bl0, bl1, bl2, bl3, baseB2l + boff);
            mma_bf16(d2[2 * p],     ha[s], bh0, bh1);
            mma_bf16(d2[2 * p],     ha[s], bl0, bl1);
            mma_bf16(d2[2 * p],     la[s], bh0, bh1);
            mma_bf16(d2[2 * p + 1], ha[s], bh2, bh3);
            mma_bf16(d2[2 * p + 1], ha[s], bl2, bl3);
            mma_bf16(d2[2 * p + 1], la[s], bh2, bh3);
        }
    }

    // ---- epilogue2: bias + GELU + dot W3 + b3 -----------------------------
    float pA = 0.f, pB = 0.f;
#pragma unroll
    for (int nt = 0; nt < 8; nt++) {
        int c0 = nt * 8 + 2 * lt;
        float w30 = s_w3[c0], w31 = s_w3[c0 + 1];
        float x0 = d2[nt][0] + s_b2[c0];
        float x1 = d2[nt][1] + s_b2[c0 + 1];
        float x2 = d2[nt][2] + s_b2[c0];
        float x3 = d2[nt][3] + s_b2[c0 + 1];
        pA = fmaf(x0 * normcdff(x0), w30, pA);
        pA = fmaf(x1 * normcdff(x1), w31, pA);
        pB = fmaf(x2 * normcdff(x2), w30, pB);
        pB = fmaf(x3 * normcdff(x3), w31, pB);
    }
#pragma unroll
    for (int msk = 1; msk < 4; msk <<= 1) {
        pA += __shfl_xor_sync(0xffffffffu, pA, msk);
        pB += __shfl_xor_sync(0xffffffffu, pB, msk);
    }
    if (lt == 0) {
        float b3v = b3[g];
        int rA = w * 16 + lg, rB = rA + 8;
        if (rA < nE) out[tileStart + rA] = pA + b3v;
        if (rB < nE) out[tileStart + rB] = pB + b3v;
    }
}

// ---------------------------------------------------------------------------
extern "C" void kernel_launch(void* const* d_in, const int* in_sizes, int n_in,
                              void* d_out, int out_size) {
    const float* emb    = (const float*)d_in[0];
    const int*   edges  = (const int*)d_in[1];
    const int*   groups = (const int*)d_in[2];
    const float* W1     = (const float*)d_in[3];
    const float* b1     = (const float*)d_in[4];
    const float* lng    = (const float*)d_in[5];
    const float* lnb    = (const float*)d_in[6];
    const float* W2     = (const float*)d_in[7];
    const float* b2     = (const float*)d_in[8];
    const float* W3     = (const float*)d_in[9];
    const float* b3     = (const float*)d_in[10];
    float* out = (float*)d_out;

    int E = in_sizes[2];
    int embElems = in_sizes[0];
    int nChunks = (E + CHUNK - 1) / CHUNK;

    int total4 = embElems / 4;
    int embBlocks = (total4 + 255) / 256;
    int w1Blocks = (W1_ELEMS + 255) / 256;
    int w2Blocks = (W2_ELEMS + 255) / 256;

    // launch order chosen so k_main is launch index 3 (ncu capture slot)
    k_prep<<<embBlocks + w1Blocks + w2Blocks, 256>>>(emb, total4, embBlocks,
                                                     W1, w1Blocks, W2);
    k_scan<<<1, SCAN_T>>>(groups, E, nChunks);
    k_scatter<<<(nChunks + 255) / 256, 256>>>(groups, E, nChunks);

    int maxTiles = (E + 127) / 128 + 3;
    k_main<<<maxTiles, 256>>>(edges, b1, lng, lnb, b2, W3, b3, out);
}

// round 17
// speedup vs baseline: 1.7881x; 1.7881x over previous
#include <cuda_runtime.h>
#include <cuda_bf16.h>
#include <math.h>
#include <stdint.h>

// Problem constants: N=100000, H=128, E=500000, G=3
#define MAX_E      600000
#define MAX_NODES  100608
#define CHUNK      128
#define MAX_CHUNKS ((MAX_E + CHUNK - 1) / CHUNK)

__device__ int d_perm[MAX_E];
__device__ int d_chunkCnt[MAX_CHUNKS * 3];
__device__ int d_chunkOff[MAX_CHUNKS * 3];
__device__ int d_groupStart[4];
__device__ int d_tileBase[4];

__device__ unsigned short d_emb_hi[MAX_NODES * 128];
__device__ unsigned short d_emb_lo[MAX_NODES * 128];
__device__ unsigned short d_w1t_hi[3 * 128 * 256];   // [g][n=128][k=256]
__device__ unsigned short d_w1t_lo[3 * 128 * 256];
__device__ unsigned short d_w2t_hi[3 * 64 * 128];    // [g][n=64][k=128]
__device__ unsigned short d_w2t_lo[3 * 64 * 128];

// ======================= helpers ============================================
__device__ __forceinline__ uint32_t smem_u32(const void* p) {
    uint32_t a;
    asm("{ .reg .u64 t; cvta.to.shared.u64 t, %1; cvt.u32.u64 %0, t; }"
        : "=r"(a) : "l"(p));
    return a;
}
__device__ __forceinline__ void ldsm4(uint32_t& r0, uint32_t& r1,
                                      uint32_t& r2, uint32_t& r3, uint32_t a) {
    asm volatile("ldmatrix.sync.aligned.m8n8.x4.shared.b16 {%0,%1,%2,%3}, [%4];"
        : "=r"(r0), "=r"(r1), "=r"(r2), "=r"(r3) : "r"(a));
}
__device__ __forceinline__ void mma_bf16(float* d, const uint32_t* a,
                                         uint32_t b0, uint32_t b1) {
    asm volatile("mma.sync.aligned.m16n8k16.row.col.f32.bf16.bf16.f32 "
        "{%0,%1,%2,%3}, {%4,%5,%6,%7}, {%8,%9}, {%0,%1,%2,%3};"
        : "+f"(d[0]), "+f"(d[1]), "+f"(d[2]), "+f"(d[3])
        : "r"(a[0]), "r"(a[1]), "r"(a[2]), "r"(a[3]), "r"(b0), "r"(b1));
}
__device__ __forceinline__ uint32_t pack_bf16x2(float x, float y) {
    __nv_bfloat162 v = __floats2bfloat162_rn(x, y);
    return *reinterpret_cast<uint32_t*>(&v);
}
#define CP16(dst, src) \
    asm volatile("cp.async.cg.shared.global [%0], [%1], 16;" \
        :: "r"(dst), "l"(src) : "memory")
#define CP_COMMIT() asm volatile("cp.async.commit_group;" ::: "memory")
#define CP_WAIT_ALL() asm volatile("cp.async.wait_group 0;" ::: "memory")

// =========================== fused prep + count =============================
__device__ __forceinline__ void split_bf16(float x, unsigned short& h, unsigned short& l) {
    __nv_bfloat16 hb = __float2bfloat16(x);
    float hf = __bfloat162float(hb);
    __nv_bfloat16 lb = __float2bfloat16(x - hf);
    h = __bfloat16_as_ushort(hb); l = __bfloat16_as_ushort(lb);
}

#define W1_ELEMS (3 * 256 * 128)
#define W2_ELEMS (3 * 128 * 64)

// blockIdx ranges: emb(float4) | W1 | W2 | chunk counting (parallel)
__global__ void k_prep(const float* __restrict__ emb, int total4, int embBlocks,
                       const float* __restrict__ W1, int w1Blocks,
                       const float* __restrict__ W2, int w2Blocks,
                       const int* __restrict__ groups, int E, int nChunks) {
    int bb = blockIdx.x;
    if (bb < embBlocks) {
        int i = bb * 256 + threadIdx.x;
        if (i >= total4) return;
        float4 v = reinterpret_cast<const float4*>(emb)[i];
        ushort4 h, l;
        split_bf16(v.x, h.x, l.x); split_bf16(v.y, h.y, l.y);
        split_bf16(v.z, h.z, l.z); split_bf16(v.w, h.w, l.w);
        reinterpret_cast<ushort4*>(d_emb_hi)[i] = h;
        reinterpret_cast<ushort4*>(d_emb_lo)[i] = l;
    } else if (bb < embBlocks + w1Blocks) {
        int i = (bb - embBlocks) * 256 + threadIdx.x;
        if (i >= W1_ELEMS) return;
        int g = i / (256 * 128), r = i % (256 * 128);
        int d = r / 128, h = r % 128;
        int dst = (g * 128 + h) * 256 + d;
        split_bf16(W1[i], d_w1t_hi[dst], d_w1t_lo[dst]);
    } else if (bb < embBlocks + w1Blocks + w2Blocks) {
        int i = (bb - embBlocks - w1Blocks) * 256 + threadIdx.x;
        if (i >= W2_ELEMS) return;
        int g = i / (128 * 64), r = i % (128 * 64);
        int k = r / 64, n = r % 64;
        int dst = (g * 64 + n) * 128 + k;
        split_bf16(W2[i], d_w2t_hi[dst], d_w2t_lo[dst]);
    } else {
        int c = (bb - embBlocks - w1Blocks - w2Blocks) * 256 + threadIdx.x;
        if (c >= nChunks) return;
        int c0 = 0, c1 = 0, c2 = 0;
        int s = c * CHUNK, e = s + CHUNK; if (e > E) e = E;
        for (int i = s; i < e; i++) {
            int g = groups[i];
            c0 += (g == 0); c1 += (g == 1); c2 += (g == 2);
        }
        d_chunkCnt[c * 3 + 0] = c0;
        d_chunkCnt[c * 3 + 1] = c1;
        d_chunkCnt[c * 3 + 2] = c2;
    }
}

// =================== scan-only (single CTA, reads d_chunkCnt) ===============
#define SCAN_T 512
__global__ void k_scan(int nChunks) {
    __shared__ int sv[SCAN_T]; __shared__ int gtot[3]; __shared__ int gs[4];
    int tid = threadIdx.x;
    int per = (nChunks + SCAN_T - 1) / SCAN_T;
    int c0 = tid * per, c1 = c0 + per;
    if (c1 > nChunks) c1 = nChunks;
    if (c0 > nChunks) c0 = nChunks;
    int t[3] = {0, 0, 0};
    for (int c = c0; c < c1; c++) {
        t[0] += d_chunkCnt[c * 3]; t[1] += d_chunkCnt[c * 3 + 1]; t[2] += d_chunkCnt[c * 3 + 2];
    }
    int base[3];
    for (int g = 0; g < 3; g++) {
        sv[tid] = t[g];
        __syncthreads();
        for (int off = 1; off < SCAN_T; off <<= 1) {
            int v = (tid >= off) ? sv[tid - off] : 0;
            __syncthreads(); sv[tid] += v; __syncthreads();
        }
        base[g] = sv[tid] - t[g];
        if (tid == SCAN_T - 1) gtot[g] = sv[tid];
        __syncthreads();
    }
    if (tid == 0) {
        gs[0] = 0; gs[1] = gtot[0]; gs[2] = gtot[0] + gtot[1]; gs[3] = gs[2] + gtot[2];
        int tb = 0;
        for (int g = 0; g < 3; g++) {
            d_groupStart[g] = gs[g]; d_tileBase[g] = tb;
            tb += (gtot[g] + 127) >> 7;
        }
        d_groupStart[3] = gs[3]; d_tileBase[3] = tb;
    }
    __syncthreads();
    int run[3];
    for (int g = 0; g < 3; g++) run[g] = gs[g] + base[g];
    for (int c = c0; c < c1; c++)
        for (int g = 0; g < 3; g++) { d_chunkOff[c * 3 + g] = run[g]; run[g] += d_chunkCnt[c * 3 + g]; }
}

__global__ void k_scatter(const int* __restrict__ groups, int E, int nChunks) {
    int c = blockIdx.x * blockDim.x + threadIdx.x;
    if (c >= nChunks) return;
    int o0 = d_chunkOff[c * 3], o1 = d_chunkOff[c * 3 + 1], o2 = d_chunkOff[c * 3 + 2];
    int s = c * CHUNK, e = s + CHUNK; if (e > E) e = E;
    for (int i = s; i < e; i++) {
        int g = groups[i];
        int p = (g == 0) ? o0++ : (g == 1) ? o1++ : o2++;
        d_perm[p] = i;
    }
}

// =============================== main kernel ================================
// 128-edge tile, 256 threads = 8 warps (warp w: rows w*16..w*16+15).
// GEMM1: K=256 in 16 chunks of 16, cp.async double-buffered, XOR-swizzled.
// Epilogue1 writes GEMM2 A-fragments IN PLACE into d1 (bit-cast) so the
// fragment arrays never coexist with d1 -> regs <= 128 -> 2 CTAs/SM.

#define BST2 136   // B2 padded row stride in bf16 (128+8)

__global__ __launch_bounds__(256, 2) void k_main(
    const int* __restrict__ edges,
    const float* __restrict__ b1, const float* __restrict__ lng,
    const float* __restrict__ lnb, const float* __restrict__ b2,
    const float* __restrict__ W3, const float* __restrict__ b3,
    float* __restrict__ out)
{
    __shared__ __align__(16) union {
        struct {
            unsigned short A[2][2][2048];   // [buf][hi/lo][128 rows x 16 k]
            unsigned short B[2][2][2048];
        } p1;                               // 32768 B
        struct {
            unsigned short B2h[64 * BST2]; unsigned short B2l[64 * BST2];
        } p2;                               // 34816 B
    } sm;
    __shared__ int sU[128], sV[128];
    __shared__ float s_b1[128], s_lng[128], s_lnb[128];
    __shared__ float s_b2[64], s_w3[64];

    int b = blockIdx.x;
    if (b >= d_tileBase[3]) return;
    int g = (b >= d_tileBase[1]) + (b >= d_tileBase[2]);
    int tileStart = d_groupStart[g] + (b - d_tileBase[g]) * 128;
    int nE = d_groupStart[g + 1] - tileStart;
    if (nE > 128) nE = 128;

    int tid = threadIdx.x;
    int w = tid >> 5, L = tid & 31;
    int lg = L >> 2, lt = L & 3;
    int m8 = L >> 3, r8 = L & 7;

    if (tid < 128) {
        int u = 0, v = 0;
        if (tid < nE) {
            int e = d_perm[tileStart + tid];
            u = edges[2 * e]; v = edges[2 * e + 1];
        }
        sU[tid] = u; sV[tid] = v;
        s_b1[tid]  = b1[g * 128 + tid];
        s_lng[tid] = lng[g * 128 + tid];
        s_lnb[tid] = lnb[g * 128 + tid];
    }
    if (tid < 64) { s_b2[tid] = b2[g * 64 + tid]; s_w3[tid] = W3[g * 64 + tid]; }
    __syncthreads();

    const unsigned short* w1h = d_w1t_hi + (size_t)g * 128 * 256;
    const unsigned short* w1l = d_w1t_lo + (size_t)g * 128 * 256;

    uint32_t baseA[2][2], baseB[2][2];
#pragma unroll
    for (int bu = 0; bu < 2; bu++)
#pragma unroll
        for (int hl = 0; hl < 2; hl++) {
            baseA[bu][hl] = smem_u32(&sm.p1.A[bu][hl][0]);
            baseB[bu][hl] = smem_u32(&sm.p1.B[bu][hl][0]);
        }

    auto issueChunk = [&](int chunk, int bu) {
        int kb = chunk * 16;
#pragma unroll
        for (int t = 0; t < 4; t++) {
            int idx = tid + t * 256;          // 0..1023
            if (idx < 512) {                  // A: 128 rows x 2 blk x 2 hl
                int row = idx >> 2;
                int hl = (idx >> 1) & 1;
                int blk = idx & 1;
                int node = (kb < 128) ? sU[row] : sV[row];
                const unsigned short* src = (hl ? d_emb_lo : d_emb_hi)
                    + (size_t)node * 128 + (kb & 127) + blk * 8;
                uint32_t dst = baseA[bu][hl]
                    + (uint32_t)(row * 32 + ((blk ^ ((row >> 2) & 1)) << 4));
                CP16(dst, src);
            } else {                          // B: 128 n x 2 blk x 2 hl
                int i = idx - 512;
                int n = i >> 2;
                int hl = (i >> 1) & 1;
                int blk = i & 1;
                const unsigned short* src = (hl ? w1l : w1h)
                    + (size_t)n * 256 + kb + blk * 8;
                uint32_t dst = baseB[bu][hl]
                    + (uint32_t)(n * 32 + ((blk ^ ((n >> 2) & 1)) << 4));
                CP16(dst, src);
            }
        }
    };

    // ---- GEMM1: D1[128,128] -----------------------------------------------
    float d1[16][4];
#pragma unroll
    for (int n = 0; n < 16; n++)
#pragma unroll
        for (int j = 0; j < 4; j++) d1[n][j] = 0.f;

    int aRow = w * 16 + r8 + (m8 & 1) * 8;
    int aBlk = m8 >> 1;
    uint32_t aOff = (uint32_t)(aRow * 32 + ((aBlk ^ ((aRow >> 2) & 1)) << 4));
    int bN = r8 + (m8 >> 1) * 8;
    int bBlk = m8 & 1;

    issueChunk(0, 0);
    CP_COMMIT();

    for (int c = 0; c < 16; c++) {
        int bu = c & 1;
        CP_WAIT_ALL();
        __syncthreads();
        if (c + 1 < 16) { issueChunk(c + 1, (c + 1) & 1); CP_COMMIT(); }

        uint32_t ah[4], al[4];
        ldsm4(ah[0], ah[1], ah[2], ah[3], baseA[bu][0] + aOff);
        ldsm4(al[0], al[1], al[2], al[3], baseA[bu][1] + aOff);
#pragma unroll
        for (int p = 0; p < 8; p++) {
            int bRow = 16 * p + bN;
            uint32_t boff = (uint32_t)(bRow * 32 + ((bBlk ^ ((bRow >> 2) & 1)) << 4));
            uint32_t bh0, bh1, bh2, bh3, bl0, bl1, bl2, bl3;
            ldsm4(bh0, bh1, bh2, bh3, baseB[bu][0] + boff);
            ldsm4(bl0, bl1, bl2, bl3, baseB[bu][1] + boff);
            mma_bf16(d1[2 * p],     ah, bh0, bh1);
            mma_bf16(d1[2 * p],     ah, bl0, bl1);
            mma_bf16(d1[2 * p],     al, bh0, bh1);
            mma_bf16(d1[2 * p + 1], ah, bh2, bh3);
            mma_bf16(d1[2 * p + 1], ah, bl2, bl3);
            mma_bf16(d1[2 * p + 1], al, bh2, bh3);
        }
    }
    __syncthreads();   // all reads of p1 done before B2 overwrites (union)

    // ---- prefetch B2 (W2T) via cp.async; overlapped with epilogue1 --------
    {
        const unsigned short* w2h = d_w2t_hi + (size_t)g * 64 * 128;
        const unsigned short* w2l = d_w2t_lo + (size_t)g * 64 * 128;
        uint32_t b2h = smem_u32(sm.p2.B2h), b2l = smem_u32(sm.p2.B2l);
#pragma unroll
        for (int t = 0; t < 8; t++) {
            int idx = tid + t * 256;          // 0..2047
            int hl = idx >> 10, i = idx & 1023;
            int n = i >> 4, q = i & 15;
            const unsigned short* src = (hl ? w2l : w2h) + (size_t)n * 128 + q * 8;
            uint32_t dst = (hl ? b2l : b2h) + (uint32_t)(n * 272 + q * 16);
            CP16(dst, src);
        }
        CP_COMMIT();
    }

    // ---- epilogue1: bias + LN + GELU; fragments written IN PLACE into d1 --
    // After this block, d1[nt] holds (as bits): [hi01, hi23, lo01, lo23]
    float sA = 0.f, sA2 = 0.f, sB = 0.f, sB2 = 0.f;
#pragma unroll
    for (int nt = 0; nt < 16; nt++) {
        int c0 = nt * 8 + 2 * lt;
        float v0 = d1[nt][0] + s_b1[c0];
        float v1 = d1[nt][1] + s_b1[c0 + 1];
        float v2 = d1[nt][2] + s_b1[c0];
        float v3 = d1[nt][3] + s_b1[c0 + 1];
        d1[nt][0] = v0; d1[nt][1] = v1; d1[nt][2] = v2; d1[nt][3] = v3;
        sA += v0 + v1; sA2 += v0 * v0 + v1 * v1;
        sB += v2 + v3; sB2 += v2 * v2 + v3 * v3;
    }
#pragma unroll
    for (int msk = 1; msk < 4; msk <<= 1) {
        sA  += __shfl_xor_sync(0xffffffffu, sA,  msk);
        sA2 += __shfl_xor_sync(0xffffffffu, sA2, msk);
        sB  += __shfl_xor_sync(0xffffffffu, sB,  msk);
        sB2 += __shfl_xor_sync(0xffffffffu, sB2, msk);
    }
    float muA = sA * (1.f / 128.f);
    float invA = rsqrtf(sA2 * (1.f / 128.f) - muA * muA + 1e-5f);
    float muB = sB * (1.f / 128.f);
    float invB = rsqrtf(sB2 * (1.f / 128.f) - muB * muB + 1e-5f);

#pragma unroll
    for (int nt = 0; nt < 16; nt++) {
        int c0 = nt * 8 + 2 * lt;
        float gl0 = s_lng[c0], gl1 = s_lng[c0 + 1];
        float bb0 = s_lnb[c0], bb1v = s_lnb[c0 + 1];
        float h0 = (d1[nt][0] - muA) * invA * gl0 + bb0;
        float h1 = (d1[nt][1] - muA) * invA * gl1 + bb1v;
        float h2 = (d1[nt][2] - muB) * invB * gl0 + bb0;
        float h3 = (d1[nt][3] - muB) * invB * gl1 + bb1v;
        h0 = h0 * normcdff(h0); h1 = h1 * normcdff(h1);
        h2 = h2 * normcdff(h2); h3 = h3 * normcdff(h3);
        float e0, e1, e2, e3;
        __nv_bfloat16 t0 = __float2bfloat16(h0); e0 = h0 - __bfloat162float(t0);
        __nv_bfloat16 t1 = __float2bfloat16(h1); e1 = h1 - __bfloat162float(t1);
        __nv_bfloat16 t2 = __float2bfloat16(h2); e2 = h2 - __bfloat162float(t2);
        __nv_bfloat16 t3 = __float2bfloat16(h3); e3 = h3 - __bfloat162float(t3);
        __nv_bfloat162 p01; p01.x = t0; p01.y = t1;
        __nv_bfloat162 p23; p23.x = t2; p23.y = t3;
        d1[nt][0] = __uint_as_float(*reinterpret_cast<uint32_t*>(&p01));
        d1[nt][1] = __uint_as_float(*reinterpret_cast<uint32_t*>(&p23));
        d1[nt][2] = __uint_as_float(pack_bf16x2(e0, e1));
        d1[nt][3] = __uint_as_float(pack_bf16x2(e2, e3));
    }

    CP_WAIT_ALL();
    __syncthreads();

    // ---- GEMM2: D2[128,64] = h[128,128] x W2T -----------------------------
    float d2[8][4];
#pragma unroll
    for (int n = 0; n < 8; n++)
#pragma unroll
        for (int j = 0; j < 4; j++) d2[n][j] = 0.f;

    uint32_t baseB2h = smem_u32(sm.p2.B2h), baseB2l = smem_u32(sm.p2.B2l);
#pragma unroll
    for (int s = 0; s < 8; s++) {
        uint32_t ah[4], al[4];
        ah[0] = __float_as_uint(d1[2 * s][0]);
        ah[1] = __float_as_uint(d1[2 * s][1]);
        ah[2] = __float_as_uint(d1[2 * s + 1][0]);
        ah[3] = __float_as_uint(d1[2 * s + 1][1]);
        al[0] = __float_as_uint(d1[2 * s][2]);
        al[1] = __float_as_uint(d1[2 * s][3]);
        al[2] = __float_as_uint(d1[2 * s + 1][2]);
        al[3] = __float_as_uint(d1[2 * s + 1][3]);
#pragma unroll
        for (int p = 0; p < 4; p++) {
            uint32_t boff = (uint32_t)(((16 * p + bN) * BST2 + s * 16 + bBlk * 8) * 2);
            uint32_t bh0, bh1, bh2, bh3, bl0, bl1, bl2, bl3;
            ldsm4(bh0, bh1, bh2, bh3, baseB2h + boff);
            ldsm4(bl0, bl1, bl2, bl3, baseB2l + boff);
            mma_bf16(d2[2 * p],     ah, bh0, bh1);
            mma_bf16(d2[2 * p],     ah, bl0, bl1);
            mma_bf16(d2[2 * p],     al, bh0, bh1);
            mma_bf16(d2[2 * p + 1], ah, bh2, bh3);
            mma_bf16(d2[2 * p + 1], ah, bl2, bl3);
            mma_bf16(d2[2 * p + 1], al, bh2, bh3);
        }
    }

    // ---- epilogue2: bias + GELU + dot W3 + b3 -----------------------------
    float pA = 0.f, pB = 0.f;
#pragma unroll
    for (int nt = 0; nt < 8; nt++) {
        int c0 = nt * 8 + 2 * lt;
        float w30 = s_w3[c0], w31 = s_w3[c0 + 1];
        float x0 = d2[nt][0] + s_b2[c0];
        float x1 = d2[nt][1] + s_b2[c0 + 1];
        float x2 = d2[nt][2] + s_b2[c0];
        float x3 = d2[nt][3] + s_b2[c0 + 1];
        pA = fmaf(x0 * normcdff(x0), w30, pA);
        pA = fmaf(x1 * normcdff(x1), w31, pA);
        pB = fmaf(x2 * normcdff(x2), w30, pB);
        pB = fmaf(x3 * normcdff(x3), w31, pB);
    }
#pragma unroll
    for (int msk = 1; msk < 4; msk <<= 1) {
        pA += __shfl_xor_sync(0xffffffffu, pA, msk);
        pB += __shfl_xor_sync(0xffffffffu, pB, msk);
    }
    if (lt == 0) {
        float b3v = b3[g];
        int rA = w * 16 + lg, rB = rA + 8;
        if (rA < nE) out[tileStart + rA] = pA + b3v;
        if (rB < nE) out[tileStart + rB] = pB + b3v;
    }
}

// ---------------------------------------------------------------------------
extern "C" void kernel_launch(void* const* d_in, const int* in_sizes, int n_in,
                              void* d_out, int out_size) {
    const float* emb    = (const float*)d_in[0];
    const int*   edges  = (const int*)d_in[1];
    const int*   groups = (const int*)d_in[2];
    const float* W1     = (const float*)d_in[3];
    const float* b1     = (const float*)d_in[4];
    const float* lng    = (const float*)d_in[5];
    const float* lnb    = (const float*)d_in[6];
    const float* W2     = (const float*)d_in[7];
    const float* b2     = (const float*)d_in[8];
    const float* W3     = (const float*)d_in[9];
    const float* b3     = (const float*)d_in[10];
    float* out = (float*)d_out;

    int E = in_sizes[2];
    int embElems = in_sizes[0];
    int nChunks = (E + CHUNK - 1) / CHUNK;

    int total4 = embElems / 4;
    int embBlocks = (total4 + 255) / 256;
    int w1Blocks = (W1_ELEMS + 255) / 256;
    int w2Blocks = (W2_ELEMS + 255) / 256;
    int cntBlocks = (nChunks + 255) / 256;

    // 4 launches; k_main last (ncu capture slot)
    k_prep<<<embBlocks + w1Blocks + w2Blocks + cntBlocks, 256>>>(
        emb, total4, embBlocks, W1, w1Blocks, W2, w2Blocks, groups, E, nChunks);
    k_scan<<<1, SCAN_T>>>(nChunks);
    k_scatter<<<(nChunks + 255) / 256, 256>>>(groups, E, nChunks);

    int maxTiles = (E + 127) / 128 + 3;
    k_main<<<maxTiles, 256>>>(edges, b1, lng, lnb, b2, W3, b3, out);
}